// round 1
// baseline (speedup 1.0000x reference)
#include <cuda_runtime.h>
#include <math.h>

#define NN 50000
#define NE 600000
#define NG 256
#define BN_EPS 1e-5f

// ---------------- scratch (device globals; no allocation allowed) ----------
__device__ float  g_h0[(size_t)NN * 64];    // h0 [N,64]; later reused as layer-1 output h2 [N,64]
__device__ float  g_xl[(size_t)NN * 256];
__device__ float  g_xr[(size_t)NN * 256];
__device__ float  g_agg[(size_t)NN * 256];  // layer0 out (h1 after BN) ; reused as layer1 agg
__device__ float  g_elog[(size_t)NE * 4];
__device__ float  g_nmax[(size_t)NN * 4];
__device__ float  g_nsum[(size_t)NN * 4];
__device__ double g_bns[256];
__device__ double g_bnss[256];
__device__ float  g_pool[NG * 64];
__device__ float  g_cnt[NG];

// ---------------- generic tiled GEMM: C = act(A[M,K]@B[K,N] + bias) --------
// BM=BN=64, BK=16, 256 threads, 4x4 register tile. K % 16 == 0, K % 4 == 0.
__global__ void gemm_bias_act(const float* __restrict__ A, const float* __restrict__ B,
                              const float* __restrict__ bias, float* __restrict__ C,
                              int M, int N, int K, int act) {
    __shared__ float As[16][64];
    __shared__ float Bs[16][64];
    const int t = threadIdx.x;
    const int m0 = blockIdx.y * 64;
    const int n0 = blockIdx.x * 64;
    const int tx = t & 15, ty = t >> 4;

    float acc[4][4];
#pragma unroll
    for (int i = 0; i < 4; i++)
#pragma unroll
        for (int j = 0; j < 4; j++) acc[i][j] = 0.f;

    const int la_m = t >> 2;          // 0..63
    const int la_k = (t & 3) * 4;     // 0,4,8,12
    const int lb_k = t >> 4;          // 0..15
    const int lb_n = (t & 15) * 4;    // 0..60

    for (int k0 = 0; k0 < K; k0 += 16) {
        // load A tile (64 x 16)
        float4 av = make_float4(0.f, 0.f, 0.f, 0.f);
        int arow = m0 + la_m;
        if (arow < M) av = *(const float4*)(A + (size_t)arow * K + k0 + la_k);
        As[la_k + 0][la_m] = av.x;
        As[la_k + 1][la_m] = av.y;
        As[la_k + 2][la_m] = av.z;
        As[la_k + 3][la_m] = av.w;
        // load B tile (16 x 64)
        float4 bv = make_float4(0.f, 0.f, 0.f, 0.f);
        if (n0 + lb_n < N) bv = *(const float4*)(B + (size_t)(k0 + lb_k) * N + n0 + lb_n);
        Bs[lb_k][lb_n + 0] = bv.x;
        Bs[lb_k][lb_n + 1] = bv.y;
        Bs[lb_k][lb_n + 2] = bv.z;
        Bs[lb_k][lb_n + 3] = bv.w;
        __syncthreads();
#pragma unroll
        for (int kk = 0; kk < 16; kk++) {
            float a[4], b[4];
#pragma unroll
            for (int i = 0; i < 4; i++) a[i] = As[kk][ty * 4 + i];
#pragma unroll
            for (int j = 0; j < 4; j++) b[j] = Bs[kk][tx * 4 + j];
#pragma unroll
            for (int i = 0; i < 4; i++)
#pragma unroll
                for (int j = 0; j < 4; j++) acc[i][j] += a[i] * b[j];
        }
        __syncthreads();
    }
#pragma unroll
    for (int i = 0; i < 4; i++) {
        int row = m0 + ty * 4 + i;
        if (row >= M) continue;
#pragma unroll
        for (int j = 0; j < 4; j++) {
            int col = n0 + tx * 4 + j;
            if (col >= N) continue;
            float v = acc[i][j] + bias[col];
            if (act == 1) v = fmaxf(v, 0.f);
            C[(size_t)row * N + col] = v;
        }
    }
}

// ---------------- edge kernels ---------------------------------------------
__device__ inline void atomicMaxF(float* addr, float v) {
    int* ia = (int*)addr;
    int old = __float_as_int(*addr);
    while (__int_as_float(old) < v) {
        int assumed = old;
        old = atomicCAS(ia, assumed, __float_as_int(v));
        if (old == assumed) break;
    }
}

// warp per edge. logit[e,h] = sum_c att[h,c]*lrelu(xl[s,h,c]+xr[d,h,c]+em[e,h,c])
__global__ void edge_logits(const float* __restrict__ xl, const float* __restrict__ xr,
                            const float* __restrict__ ea, const float* __restrict__ We,
                            const float* __restrict__ att,
                            const int* __restrict__ src, const int* __restrict__ dst,
                            float* __restrict__ elog, float* __restrict__ nmax, int E) {
    __shared__ float We_sh[16 * 256];
    __shared__ float att_sh[256];
    const int t = threadIdx.x;
    for (int i = t; i < 16 * 256; i += blockDim.x) We_sh[i] = We[i];
    if (t < 256) att_sh[t] = att[t];
    __syncthreads();

    const int lane = t & 31;
    const int e = blockIdx.x * (blockDim.x >> 5) + (t >> 5);
    if (e >= E) return;
    const int s = src[e], d = dst[e];
    float eav = (lane < 16) ? ea[(size_t)e * 16 + lane] : 0.f;
    const float* xls = xl + (size_t)s * 256;
    const float* xrd = xr + (size_t)d * 256;
    float hp[4] = {0.f, 0.f, 0.f, 0.f};
#pragma unroll
    for (int j = 0; j < 8; j++) {
        const int c = j * 32 + lane;
        float em = 0.f;
#pragma unroll
        for (int f = 0; f < 16; f++)
            em = fmaf(__shfl_sync(0xffffffffu, eav, f), We_sh[f * 256 + c], em);
        float z = xls[c] + xrd[c] + em;
        z = (z > 0.f) ? z : 0.2f * z;
        hp[j >> 1] = fmaf(z, att_sh[c], hp[j >> 1]);
    }
    float tot[4];
#pragma unroll
    for (int h = 0; h < 4; h++) {
        float v = hp[h];
#pragma unroll
        for (int o = 16; o > 0; o >>= 1) v += __shfl_xor_sync(0xffffffffu, v, o);
        tot[h] = v;
    }
    if (lane < 4) {
        float l = tot[lane];
        elog[(size_t)e * 4 + lane] = l;
        atomicMaxF(&nmax[(size_t)d * 4 + lane], l);
    }
}

__global__ void edge_exp(const int* __restrict__ dst, float* __restrict__ elog,
                         const float* __restrict__ nmax, float* __restrict__ nsum, int E) {
    int i = blockIdx.x * blockDim.x + threadIdx.x;
    if (i >= E * 4) return;
    int e = i >> 2, h = i & 3;
    int d = dst[e];
    float v = expf(elog[i] - nmax[(size_t)d * 4 + h]);
    elog[i] = v;
    atomicAdd(&nsum[(size_t)d * 4 + h], v);
}

// warp per edge: agg[d, h*64+cc] += alpha[e,h] * xl[s, h*64+cc]
__global__ void edge_agg(const float* __restrict__ xl, const int* __restrict__ src,
                         const int* __restrict__ dst, const float* __restrict__ elog,
                         const float* __restrict__ nsum, float* __restrict__ agg, int E) {
    const int t = threadIdx.x;
    const int lane = t & 31;
    const int e = blockIdx.x * (blockDim.x >> 5) + (t >> 5);
    if (e >= E) return;
    const int s = src[e], d = dst[e];
    float a4 = 0.f;
    if (lane < 4) a4 = elog[(size_t)e * 4 + lane] / (nsum[(size_t)d * 4 + lane] + 1e-16f);
    const float* xls = xl + (size_t)s * 256;
    float* ag = agg + (size_t)d * 256;
#pragma unroll
    for (int j = 0; j < 8; j++) {
        const int c = j * 32 + lane;
        float al = __shfl_sync(0xffffffffu, a4, j >> 1);
        atomicAdd(&ag[c], al * xls[c]);
    }
}

// ---------------- batch norm ------------------------------------------------
__global__ void bn_stats(const float* __restrict__ h, double* __restrict__ sum,
                         double* __restrict__ sumsq, int N, int Cf, int rowsPerBlock) {
    const int t = threadIdx.x;
    const int col = t % Cf;
    const int rpb = blockDim.x / Cf;
    int r0 = blockIdx.x * rowsPerBlock;
    int rend = min(N, r0 + rowsPerBlock);
    double s = 0.0, ss = 0.0;
    for (int r = r0 + t / Cf; r < rend; r += rpb) {
        double v = (double)h[(size_t)r * Cf + col];
        s += v;
        ss += v * v;
    }
    atomicAdd(&sum[col], s);
    atomicAdd(&sumsq[col], ss);
}

__global__ void bn_apply(float* __restrict__ h, const double* __restrict__ sum,
                         const double* __restrict__ sumsq, const float* __restrict__ gamma,
                         const float* __restrict__ beta, int N, int Cf, int doRelu) {
    size_t i = (size_t)blockIdx.x * blockDim.x + threadIdx.x;
    if (i >= (size_t)N * Cf) return;
    int col = (int)(i % Cf);
    float mu = (float)(sum[col] / N);
    float var = (float)(sumsq[col] / N) - mu * mu;
    float v = gamma[col] * (h[i] - mu) * rsqrtf(var + BN_EPS) + beta[col];
    if (doRelu) v = fmaxf(v, 0.f);
    h[i] = v;
}

// ---------------- misc small kernels ----------------------------------------
__global__ void fill_neg_inf(float* p, int n) {
    int i = blockIdx.x * blockDim.x + threadIdx.x;
    if (i < n) p[i] = -INFINITY;
}

__global__ void mean_heads(const float* __restrict__ agg, float* __restrict__ out, int N) {
    int i = blockIdx.x * blockDim.x + threadIdx.x;
    if (i >= N * 64) return;
    int n = i >> 6, c = i & 63;
    const float* a = agg + (size_t)n * 256;
    out[i] = 0.25f * (a[c] + a[64 + c] + a[128 + c] + a[192 + c]);
}

__global__ void pool_kernel(const float* __restrict__ h, const int* __restrict__ batch,
                            float* __restrict__ pooled, float* __restrict__ cnt, int N) {
    int i = blockIdx.x * blockDim.x + threadIdx.x;
    if (i >= N * 64) return;
    int n = i >> 6, c = i & 63;
    int b = batch[n];
    atomicAdd(&pooled[b * 64 + c], h[i]);
    if (c == 0) atomicAdd(&cnt[b], 1.f);
}

__global__ void mlp_kernel(const float* __restrict__ pooled, const float* __restrict__ cnt,
                           const float* __restrict__ Wm1, const float* __restrict__ bm1,
                           const float* __restrict__ Wm2, const float* __restrict__ bm2,
                           const float* __restrict__ Wm3, const float* __restrict__ bm3,
                           float* __restrict__ out) {
    __shared__ float w1[64 * 32], w2[32 * 16], w3[16];
    int t = threadIdx.x;
    for (int i = t; i < 64 * 32; i += 256) w1[i] = Wm1[i];
    for (int i = t; i < 32 * 16; i += 256) w2[i] = Wm2[i];
    if (t < 16) w3[t] = Wm3[t];
    __syncthreads();
    // one thread per graph
    float p[64];
    float c = fmaxf(cnt[t], 1.f);
#pragma unroll
    for (int f = 0; f < 64; f++) p[f] = pooled[t * 64 + f] / c;
    float z1[32];
#pragma unroll
    for (int j = 0; j < 32; j++) {
        float v = bm1[j];
#pragma unroll
        for (int f = 0; f < 64; f++) v = fmaf(p[f], w1[f * 32 + j], v);
        z1[j] = fmaxf(v, 0.f);
    }
    float z2[16];
#pragma unroll
    for (int j = 0; j < 16; j++) {
        float v = bm2[j];
#pragma unroll
        for (int f = 0; f < 32; f++) v = fmaf(z1[f], w2[f * 16 + j], v);
        z2[j] = fmaxf(v, 0.f);
    }
    float o = bm3[0];
#pragma unroll
    for (int f = 0; f < 16; f++) o = fmaf(z2[f], w3[f], o);
    out[t] = o;
}

// ---------------- launch -----------------------------------------------------
extern "C" void kernel_launch(void* const* d_in, const int* in_sizes, int n_in,
                              void* d_out, int out_size) {
    // map inputs: edge_index (2*E ints) and batch (N ints) found by unique sizes;
    // remaining float tensors keep their relative order in either metadata layout.
    const float* f[28];
    int nf = 0, idx_ei = -1, idx_b = -1;
    for (int i = 0; i < n_in; i++) {
        if (idx_ei < 0 && in_sizes[i] == 2 * NE) { idx_ei = i; continue; }
        if (idx_b < 0 && in_sizes[i] == NN) { idx_b = i; continue; }
        if (nf < 28) f[nf++] = (const float*)d_in[i];
    }
    const float *x = f[0], *edge_attr = f[1], *W_in = f[2], *b_in = f[3];
    const float *Wl0 = f[4], *bl0 = f[5], *Wr0 = f[6], *br0 = f[7], *We0 = f[8];
    const float *att0 = f[9] /* bias0=f[10] cancels in BN */, *g0 = f[11], *beta0 = f[12];
    const float *Wl1 = f[13], *bl1 = f[14], *Wr1 = f[15], *br1 = f[16], *We1 = f[17];
    const float *att1 = f[18] /* bias1=f[19] cancels in BN */, *g1 = f[20], *beta1 = f[21];
    const float *Wm1 = f[22], *bm1 = f[23], *Wm2 = f[24], *bm2 = f[25], *Wm3 = f[26], *bm3 = f[27];
    const int* edge_index = (const int*)d_in[idx_ei];
    const int* src = edge_index;
    const int* dst = edge_index + NE;
    const int* batch = (const int*)d_in[idx_b];
    float* out = (float*)d_out;

    void *p_h0, *p_xl, *p_xr, *p_agg, *p_elog, *p_nmax, *p_nsum, *p_bns, *p_bnss, *p_pool, *p_cnt;
    cudaGetSymbolAddress(&p_h0, g_h0);
    cudaGetSymbolAddress(&p_xl, g_xl);
    cudaGetSymbolAddress(&p_xr, g_xr);
    cudaGetSymbolAddress(&p_agg, g_agg);
    cudaGetSymbolAddress(&p_elog, g_elog);
    cudaGetSymbolAddress(&p_nmax, g_nmax);
    cudaGetSymbolAddress(&p_nsum, g_nsum);
    cudaGetSymbolAddress(&p_bns, g_bns);
    cudaGetSymbolAddress(&p_bnss, g_bnss);
    cudaGetSymbolAddress(&p_pool, g_pool);
    cudaGetSymbolAddress(&p_cnt, g_cnt);
    float* h0 = (float*)p_h0;
    float* xl = (float*)p_xl;
    float* xr = (float*)p_xr;
    float* agg = (float*)p_agg;
    float* elog = (float*)p_elog;
    float* nmax = (float*)p_nmax;
    float* nsum = (float*)p_nsum;
    double* bns = (double*)p_bns;
    double* bnss = (double*)p_bnss;
    float* pool = (float*)p_pool;
    float* cnt = (float*)p_cnt;

    auto gemm = [&](const float* A, const float* B, const float* bias, float* C,
                    int M, int N, int K, int act) {
        dim3 grid((N + 63) / 64, (M + 63) / 64);
        gemm_bias_act<<<grid, 256>>>(A, B, bias, C, M, N, K, act);
    };

    const int EB = (NE + 7) / 8;             // warp per edge, 8 warps/block
    const int ROWS = 512;                     // bn_stats rows per block
    const int bnBlocks = (NN + ROWS - 1) / ROWS;

    // ---- input projection
    gemm(x, W_in, b_in, h0, NN, 64, 64, 1);

    // ---- GATv2 layer 0
    gemm(h0, Wl0, bl0, xl, NN, 256, 64, 0);
    gemm(h0, Wr0, br0, xr, NN, 256, 64, 0);
    fill_neg_inf<<<(NN * 4 + 255) / 256, 256>>>(nmax, NN * 4);
    cudaMemsetAsync(nsum, 0, (size_t)NN * 4 * sizeof(float));
    cudaMemsetAsync(agg, 0, (size_t)NN * 256 * sizeof(float));
    edge_logits<<<EB, 256>>>(xl, xr, edge_attr, We0, att0, src, dst, elog, nmax, NE);
    edge_exp<<<(NE * 4 + 255) / 256, 256>>>(dst, elog, nmax, nsum, NE);
    edge_agg<<<EB, 256>>>(xl, src, dst, elog, nsum, agg, NE);
    // BN0 + relu (bias0 cancels inside BN)
    cudaMemsetAsync(bns, 0, 256 * sizeof(double));
    cudaMemsetAsync(bnss, 0, 256 * sizeof(double));
    bn_stats<<<bnBlocks, 256>>>(agg, bns, bnss, NN, 256, ROWS);
    bn_apply<<<(NN * 256 + 255) / 256, 256>>>(agg, bns, bnss, g0, beta0, NN, 256, 1);

    // ---- GATv2 layer 1 (input = agg, i.e. h1)
    gemm(agg, Wl1, bl1, xl, NN, 256, 256, 0);
    gemm(agg, Wr1, br1, xr, NN, 256, 256, 0);
    fill_neg_inf<<<(NN * 4 + 255) / 256, 256>>>(nmax, NN * 4);
    cudaMemsetAsync(nsum, 0, (size_t)NN * 4 * sizeof(float));
    cudaMemsetAsync(agg, 0, (size_t)NN * 256 * sizeof(float));
    edge_logits<<<EB, 256>>>(xl, xr, edge_attr, We1, att1, src, dst, elog, nmax, NE);
    edge_exp<<<(NE * 4 + 255) / 256, 256>>>(dst, elog, nmax, nsum, NE);
    edge_agg<<<EB, 256>>>(xl, src, dst, elog, nsum, agg, NE);
    // mean over heads -> h2 [N,64] (reuse h0 buffer); bias1 cancels in BN
    mean_heads<<<(NN * 64 + 255) / 256, 256>>>(agg, h0, NN);
    cudaMemsetAsync(bns, 0, 256 * sizeof(double));
    cudaMemsetAsync(bnss, 0, 256 * sizeof(double));
    bn_stats<<<bnBlocks, 256>>>(h0, bns, bnss, NN, 64, ROWS);
    bn_apply<<<(NN * 64 + 255) / 256, 256>>>(h0, bns, bnss, g1, beta1, NN, 64, 0);

    // ---- global mean pool + MLP head
    cudaMemsetAsync(pool, 0, NG * 64 * sizeof(float));
    cudaMemsetAsync(cnt, 0, NG * sizeof(float));
    pool_kernel<<<(NN * 64 + 255) / 256, 256>>>(h0, batch, pool, cnt, NN);
    mlp_kernel<<<1, 256>>>(pool, cnt, Wm1, bm1, Wm2, bm2, Wm3, bm3, out);
}